// round 15
// baseline (speedup 1.0000x reference)
#include <cuda_runtime.h>

#define TPB 256

// ---- shared-memory layout (floats), float4-aligned bases ----
// Hidden matrices transposed to [out_j][in_k], rows padded to 32 (w-MLP) or
// 16 (phi-MLP). Bias folded into slot 30 (resp. 15); activation lane pinned 1.
// After the preamble TRANSFORM phase, activations are sigma = 1/(1+exp2(z)):
//   hidden weights scaled by -4*log2(e), biases -> 2log2e*(b + row_sum)
//   output weights scaled by -2,          biases -> b + row_sum
//   layer-1 weights/biases scaled by 2*log2(e)
namespace off {
constexpr int W1  = 0;     // [2][32]   (pad of [2][30])
constexpr int B1  = 64;    // [32]
constexpr int W2T = 96;    // [30][32]  slot30=bias, slot31=0
constexpr int W3T = 1056;  // [30][32]
constexpr int W4T = 2016;  // [8][32]
constexpr int P1  = 2272;  // [2][16]   (pad of [2][15])
constexpr int PB1 = 2304;  // [16]
constexpr int P2T = 2320;  // [15][16]  slot15=bias
constexpr int P3T = 2560;  // [15][16]
constexpr int P4T = 2800;  // [4][16]
constexpr int IMV = 2864;  // [2]
constexpr int LMB = 2866;  // [1]
constexpr int TOTAL = 2868;
}

#define L2E2   2.8853900817779268f      // 2*log2(e)
#define NL2E4 -5.7707801635558537f      // -4*log2(e)

// sigma(z) = 1/(1 + exp2(z)); tanh folded into surrounding weights.
// 1 fma-pipe add + 2 MUFU. Saturates correctly (exp2 -> inf/0).
__device__ __forceinline__ float sigma_act(float z) {
    float e;
    asm("ex2.approx.f32 %0, %1;" : "=f"(e) : "f"(z));
    float rc;
    float d = 1.0f + e;
    asm("rcp.approx.f32 %0, %1;" : "=f"(rc) : "f"(d));
    return rc;
}

// Branchless half-angle: (c,s) on unit circle -> sin(th/2), cos(th/2).
__device__ __forceinline__ void half_angle(float c, float s, float& sh, float& ch) {
    float root = sqrtf(0.5f * (1.0f + fabsf(c)));
    float q    = __fdividef(s, 2.0f * root);
    bool pos   = (c >= 0.0f);
    sh = pos ? q    : copysignf(root, s);
    ch = pos ? root : fabsf(q);
}

__global__ void __launch_bounds__(TPB)
mlp_interior_kernel(
    const float* __restrict__ x,
    const float* __restrict__ imv,
    const float* __restrict__ lmbd,
    const float* __restrict__ Ww1, const float* __restrict__ bw1,
    const float* __restrict__ Ww2, const float* __restrict__ bw2,
    const float* __restrict__ Ww3, const float* __restrict__ bw3,
    const float* __restrict__ Ww4, const float* __restrict__ bw4,
    const float* __restrict__ Wp1, const float* __restrict__ bp1,
    const float* __restrict__ Wp2, const float* __restrict__ bp2,
    const float* __restrict__ Wp3, const float* __restrict__ bp3,
    const float* __restrict__ Wp4, const float* __restrict__ bp4,
    float* __restrict__ out, int N)
{
    __shared__ float S[off::TOTAL];
    const int tid = threadIdx.x;

    // ---- fill phase (unscaled, transposed, bias in slot30/15) ----
    for (int k = tid; k < off::TOTAL; k += TPB) S[k] = 0.0f;
    __syncthreads();

    for (int t = tid; t < 60; t += TPB)  S[off::W1  + (t / 30) * 32 + (t % 30)] = Ww1[t];
    for (int t = tid; t < 30; t += TPB)  S[off::B1  + t] = bw1[t];
    for (int t = tid; t < 900; t += TPB) S[off::W2T + (t % 30) * 32 + (t / 30)] = Ww2[t];
    for (int t = tid; t < 30; t += TPB)  S[off::W2T + t * 32 + 30] = bw2[t];
    for (int t = tid; t < 900; t += TPB) S[off::W3T + (t % 30) * 32 + (t / 30)] = Ww3[t];
    for (int t = tid; t < 30; t += TPB)  S[off::W3T + t * 32 + 30] = bw3[t];
    for (int t = tid; t < 240; t += TPB) S[off::W4T + (t % 8) * 32 + (t / 8)]   = Ww4[t];
    for (int t = tid; t < 8;  t += TPB)  S[off::W4T + t * 32 + 30] = bw4[t];
    for (int t = tid; t < 30; t += TPB)  S[off::P1  + (t / 15) * 16 + (t % 15)] = Wp1[t];
    for (int t = tid; t < 15; t += TPB)  S[off::PB1 + t] = bp1[t];
    for (int t = tid; t < 225; t += TPB) S[off::P2T + (t % 15) * 16 + (t / 15)] = Wp2[t];
    for (int t = tid; t < 15; t += TPB)  S[off::P2T + t * 16 + 15] = bp2[t];
    for (int t = tid; t < 225; t += TPB) S[off::P3T + (t % 15) * 16 + (t / 15)] = Wp3[t];
    for (int t = tid; t < 15; t += TPB)  S[off::P3T + t * 16 + 15] = bp3[t];
    for (int t = tid; t < 60; t += TPB)  S[off::P4T + (t % 4) * 16 + (t / 4)]   = Wp4[t];
    for (int t = tid; t < 4;  t += TPB)  S[off::P4T + t * 16 + 15] = bp4[t];
    if (tid == 0) {
        S[off::IMV]     = imv[0];
        S[off::IMV + 1] = imv[1];
        S[off::LMB]     = lmbd[0];
    }
    __syncthreads();

    // ---- transform phase (sigma-activation algebra folded into weights) ----
    for (int t = tid; t < 60; t += TPB) {          // W2T, W3T rows
        int base = (t < 30 ? off::W2T : off::W3T) + (t % 30) * 32;
        float sum = 0.0f;
        for (int k = 0; k < 30; ++k) sum += S[base + k];
        S[base + 30] = L2E2 * (S[base + 30] + sum);
        for (int k = 0; k < 30; ++k) S[base + k] *= NL2E4;
    }
    for (int t = tid; t < 8; t += TPB) {           // W4T (output layer)
        int base = off::W4T + t * 32;
        float sum = 0.0f;
        for (int k = 0; k < 30; ++k) sum += S[base + k];
        S[base + 30] += sum;
        for (int k = 0; k < 30; ++k) S[base + k] *= -2.0f;
    }
    for (int t = tid; t < 30; t += TPB) {          // P2T, P3T rows
        int base = (t < 15 ? off::P2T : off::P3T) + (t % 15) * 16;
        float sum = 0.0f;
        for (int k = 0; k < 15; ++k) sum += S[base + k];
        S[base + 15] = L2E2 * (S[base + 15] + sum);
        for (int k = 0; k < 15; ++k) S[base + k] *= NL2E4;
    }
    for (int t = tid; t < 4; t += TPB) {           // P4T (output layer)
        int base = off::P4T + t * 16;
        float sum = 0.0f;
        for (int k = 0; k < 15; ++k) sum += S[base + k];
        S[base + 15] += sum;
        for (int k = 0; k < 15; ++k) S[base + k] *= -2.0f;
    }
    for (int t = tid; t < 60; t += TPB) S[off::W1 + (t / 30) * 32 + (t % 30)] *= L2E2;
    for (int t = tid; t < 30; t += TPB) S[off::B1 + t] *= L2E2;
    for (int t = tid; t < 30; t += TPB) S[off::P1 + (t / 15) * 16 + (t % 15)] *= L2E2;
    for (int t = tid; t < 15; t += TPB) S[off::PB1 + t] *= L2E2;
    __syncthreads();

    const int i = blockIdx.x * TPB + tid;
    if (i >= N) return;

    const float2 xv = reinterpret_cast<const float2*>(x)[i];
    const float x0 = xv.x, x1 = xv.y;

    // ---------- w MLP: 2 -> 30 -> 30 -> 30 -> 8 (sigma activations) ----------
    float h[32], g[32];
    #pragma unroll
    for (int c = 0; c < 8; ++c) {
        float4 w0 = *reinterpret_cast<const float4*>(&S[off::W1 + 4 * c]);
        float4 w1 = *reinterpret_cast<const float4*>(&S[off::W1 + 32 + 4 * c]);
        float4 bb = *reinterpret_cast<const float4*>(&S[off::B1 + 4 * c]);
        h[4 * c + 0] = sigma_act(fmaf(x0, w0.x, fmaf(x1, w1.x, bb.x)));
        h[4 * c + 1] = sigma_act(fmaf(x0, w0.y, fmaf(x1, w1.y, bb.y)));
        h[4 * c + 2] = sigma_act(fmaf(x0, w0.z, fmaf(x1, w1.z, bb.z)));
        h[4 * c + 3] = sigma_act(fmaf(x0, w0.w, fmaf(x1, w1.w, bb.w)));
    }
    h[30] = 1.0f; h[31] = 0.0f;          // bias lane / zero pad
    #pragma unroll
    for (int j = 0; j < 30; ++j) {
        const float4* row = reinterpret_cast<const float4*>(&S[off::W2T + j * 32]);
        float a0 = 0.f, a1 = 0.f, a2 = 0.f, a3 = 0.f;
        #pragma unroll
        for (int c = 0; c < 8; ++c) {
            float4 wv = row[c];
            a0 = fmaf(h[4 * c + 0], wv.x, a0);
            a1 = fmaf(h[4 * c + 1], wv.y, a1);
            a2 = fmaf(h[4 * c + 2], wv.z, a2);
            a3 = fmaf(h[4 * c + 3], wv.w, a3);
        }
        g[j] = sigma_act((a0 + a1) + (a2 + a3));
    }
    g[30] = 1.0f; g[31] = 0.0f;
    #pragma unroll
    for (int j = 0; j < 30; ++j) {
        const float4* row = reinterpret_cast<const float4*>(&S[off::W3T + j * 32]);
        float a0 = 0.f, a1 = 0.f, a2 = 0.f, a3 = 0.f;
        #pragma unroll
        for (int c = 0; c < 8; ++c) {
            float4 wv = row[c];
            a0 = fmaf(g[4 * c + 0], wv.x, a0);
            a1 = fmaf(g[4 * c + 1], wv.y, a1);
            a2 = fmaf(g[4 * c + 2], wv.z, a2);
            a3 = fmaf(g[4 * c + 3], wv.w, a3);
        }
        h[j] = sigma_act((a0 + a1) + (a2 + a3));
    }
    h[30] = 1.0f; h[31] = 0.0f;
    float w[8];
    #pragma unroll
    for (int j = 0; j < 8; ++j) {
        const float4* row = reinterpret_cast<const float4*>(&S[off::W4T + j * 32]);
        float a0 = 0.f, a1 = 0.f, a2 = 0.f, a3 = 0.f;
        #pragma unroll
        for (int c = 0; c < 8; ++c) {
            float4 wv = row[c];
            a0 = fmaf(h[4 * c + 0], wv.x, a0);
            a1 = fmaf(h[4 * c + 1], wv.y, a1);
            a2 = fmaf(h[4 * c + 2], wv.z, a2);
            a3 = fmaf(h[4 * c + 3], wv.w, a3);
        }
        w[j] = (a0 + a1) + (a2 + a3);
    }

    // ---------- geometry ----------
    const float d0 = x0 - S[off::IMV], d1 = x1 - S[off::IMV + 1];
    const float r  = sqrtf(fmaf(d0, d0, d1 * d1));
    const float ir = __fdividef(1.0f, r);
    const float bx = d0 * ir, by = d1 * ir;

    const float t  = fminf(fmaxf(fmaf(2.5f, r, -1.25f), 0.0f), 1.0f);
    const float t3 = t * t * t;
    const float yita = fmaf(fmaf(fmaf(-6.0f, t, 15.0f), t, -10.0f), t3, 1.0f);

    // ---------- phi MLP on unit vector: 2 -> 15 -> 15 -> 15 -> 4 ----------
    float p[16], q[16];
    #pragma unroll
    for (int c = 0; c < 4; ++c) {
        float4 w0 = *reinterpret_cast<const float4*>(&S[off::P1 + 4 * c]);
        float4 w1 = *reinterpret_cast<const float4*>(&S[off::P1 + 16 + 4 * c]);
        float4 bb = *reinterpret_cast<const float4*>(&S[off::PB1 + 4 * c]);
        p[4 * c + 0] = sigma_act(fmaf(bx, w0.x, fmaf(by, w1.x, bb.x)));
        p[4 * c + 1] = sigma_act(fmaf(bx, w0.y, fmaf(by, w1.y, bb.y)));
        p[4 * c + 2] = sigma_act(fmaf(bx, w0.z, fmaf(by, w1.z, bb.z)));
        p[4 * c + 3] = sigma_act(fmaf(bx, w0.w, fmaf(by, w1.w, bb.w)));
    }
    p[15] = 1.0f;                        // bias lane
    #pragma unroll
    for (int j = 0; j < 15; ++j) {
        const float4* row = reinterpret_cast<const float4*>(&S[off::P2T + j * 16]);
        float a0 = 0.f, a1 = 0.f, a2 = 0.f, a3 = 0.f;
        #pragma unroll
        for (int c = 0; c < 4; ++c) {
            float4 wv = row[c];
            a0 = fmaf(p[4 * c + 0], wv.x, a0);
            a1 = fmaf(p[4 * c + 1], wv.y, a1);
            a2 = fmaf(p[4 * c + 2], wv.z, a2);
            a3 = fmaf(p[4 * c + 3], wv.w, a3);
        }
        q[j] = sigma_act((a0 + a1) + (a2 + a3));
    }
    q[15] = 1.0f;
    #pragma unroll
    for (int j = 0; j < 15; ++j) {
        const float4* row = reinterpret_cast<const float4*>(&S[off::P3T + j * 16]);
        float a0 = 0.f, a1 = 0.f, a2 = 0.f, a3 = 0.f;
        #pragma unroll
        for (int c = 0; c < 4; ++c) {
            float4 wv = row[c];
            a0 = fmaf(q[4 * c + 0], wv.x, a0);
            a1 = fmaf(q[4 * c + 1], wv.y, a1);
            a2 = fmaf(q[4 * c + 2], wv.z, a2);
            a3 = fmaf(q[4 * c + 3], wv.w, a3);
        }
        p[j] = sigma_act((a0 + a1) + (a2 + a3));
    }
    p[15] = 1.0f;
    float ph[4];
    #pragma unroll
    for (int j = 0; j < 4; ++j) {
        const float4* row = reinterpret_cast<const float4*>(&S[off::P4T + j * 16]);
        float a0 = 0.f, a1 = 0.f, a2 = 0.f, a3 = 0.f;
        #pragma unroll
        for (int c = 0; c < 4; ++c) {
            float4 wv = row[c];
            a0 = fmaf(p[4 * c + 0], wv.x, a0);
            a1 = fmaf(p[4 * c + 1], wv.y, a1);
            a2 = fmaf(p[4 * c + 2], wv.z, a2);
            a3 = fmaf(p[4 * c + 3], wv.w, a3);
        }
        ph[j] = (a0 + a1) + (a2 + a3);
    }

    // ---------- vphi at x: r^k sin(k*theta), k = 0.5, 1.0, 1.5 ----------
    const float rr  = sqrtf(fmaf(x0, x0, x1 * x1));
    const float irr = __fdividef(1.0f, rr);
    const float cc  = x0 * irr, ss = x1 * irr;
    float sh, ch;
    half_angle(cc, ss, sh, ch);
    const float sqr = sqrtf(rr);
    const float vp0 = sqr * sh;
    const float vp1 = rr * ss;
    const float vp2 = (rr * sqr) * fmaf(ss, ch, cc * sh);

    // ---------- vphi_sig at x_ba ----------
    float shb, chb;
    half_angle(bx, by, shb, chb);
    const float vs2 = fmaf(by, chb, bx * shb);

    // ---------- combine ----------
    const float rp = w[0] + yita * w[4]
                   + fmaf(yita, w[5], w[1]) * vp0
                   + fmaf(yita, w[6], w[2]) * vp1
                   + fmaf(yita, w[7], w[3]) * vp2;
    const float sv = ph[0] + ph[1] * shb + ph[2] * by + ph[3] * vs2;

    const float lm = S[off::LMB];
    const float rl = (lm == 0.5f) ? sqrtf(r) : __powf(r, lm);

    out[i] = fmaf(sv * yita, rl, rp);
}

extern "C" void kernel_launch(void* const* d_in, const int* in_sizes, int n_in,
                              void* d_out, int out_size) {
    const float* x    = (const float*)d_in[0];
    const float* imv  = (const float*)d_in[1];
    const float* lmbd = (const float*)d_in[2];
    const float* Ww1  = (const float*)d_in[3];
    const float* bw1  = (const float*)d_in[4];
    const float* Ww2  = (const float*)d_in[5];
    const float* bw2  = (const float*)d_in[6];
    const float* Ww3  = (const float*)d_in[7];
    const float* bw3  = (const float*)d_in[8];
    const float* Ww4  = (const float*)d_in[9];
    const float* bw4  = (const float*)d_in[10];
    const float* Wp1  = (const float*)d_in[11];
    const float* bp1  = (const float*)d_in[12];
    const float* Wp2  = (const float*)d_in[13];
    const float* bp2  = (const float*)d_in[14];
    const float* Wp3  = (const float*)d_in[15];
    const float* bp3  = (const float*)d_in[16];
    const float* Wp4  = (const float*)d_in[17];
    const float* bp4  = (const float*)d_in[18];
    float* out = (float*)d_out;

    const int N = out_size;
    const int blocks = (N + TPB - 1) / TPB;
    mlp_interior_kernel<<<blocks, TPB>>>(
        x, imv, lmbd,
        Ww1, bw1, Ww2, bw2, Ww3, bw3, Ww4, bw4,
        Wp1, bp1, Wp2, bp2, Wp3, bp3, Wp4, bp4,
        out, N);
}

// round 16
// speedup vs baseline: 1.1335x; 1.1335x over previous
#include <cuda_runtime.h>

#define TPB 256
typedef unsigned long long ull;

// ---- shared-memory layout (floats), float4-aligned bases ----
// Hidden matrices transposed to [out_j][in_k], rows padded to 32 (w-MLP) or
// 16 (phi-MLP). Bias folded into slot 30 (resp. 15); activation lane pinned 1.
namespace off {
constexpr int W1  = 0;     // [2][32]   (pad of [2][30])
constexpr int B1  = 64;    // [32]
constexpr int W2T = 96;    // [30][32]  slot30=bias, slot31=0
constexpr int W3T = 1056;  // [30][32]
constexpr int W4T = 2016;  // [8][32]
constexpr int P1  = 2272;  // [2][16]   (pad of [2][15])
constexpr int PB1 = 2304;  // [16]
constexpr int P2T = 2320;  // [15][16]  slot15=bias
constexpr int P3T = 2560;  // [15][16]
constexpr int P4T = 2800;  // [4][16]
constexpr int IMV = 2864;  // [2]
constexpr int LMB = 2866;  // [1]
constexpr int TOTAL = 2868;
}

// ---- packed f32x2 helpers (operands are natural LDS.128 register pairs) ----
__device__ __forceinline__ ull pk2(float lo, float hi) {
    ull r; asm("mov.b64 %0, {%1, %2};" : "=l"(r) : "f"(lo), "f"(hi)); return r;
}
__device__ __forceinline__ void upk2(ull v, float& lo, float& hi) {
    asm("mov.b64 {%0, %1}, %2;" : "=f"(lo), "=f"(hi) : "l"(v));
}
__device__ __forceinline__ ull ffma2(ull a, ull b, ull c) {
    ull d; asm("fma.rn.f32x2 %0, %1, %2, %3;" : "=l"(d) : "l"(a), "l"(b), "l"(c)); return d;
}
__device__ __forceinline__ ull fadd2(ull a, ull b) {
    ull d; asm("add.rn.f32x2 %0, %1, %2;" : "=l"(d) : "l"(a), "l"(b)); return d;
}

// tanh(x) = 1 - 2/(1 + exp2(2*log2e*x)); ~1e-7 abs err, correct saturation.
__device__ __forceinline__ float fast_tanhf(float v) {
    float z = v * 2.8853900817779268f;     // 2*log2(e)
    float e;
    asm("ex2.approx.f32 %0, %1;" : "=f"(e) : "f"(z));
    float d = e + 1.0f;
    float rc;
    asm("rcp.approx.f32 %0, %1;" : "=f"(rc) : "f"(d));
    return fmaf(-2.0f, rc, 1.0f);
}

// Branchless half-angle: (c,s) on unit circle -> sin(th/2), cos(th/2).
__device__ __forceinline__ void half_angle(float c, float s, float& sh, float& ch) {
    float root = sqrtf(0.5f * (1.0f + fabsf(c)));
    float q    = __fdividef(s, 2.0f * root);
    bool pos   = (c >= 0.0f);
    sh = pos ? q    : copysignf(root, s);
    ch = pos ? root : fabsf(q);
}

__global__ void __launch_bounds__(TPB)
mlp_interior_kernel(
    const float* __restrict__ x,
    const float* __restrict__ imv,
    const float* __restrict__ lmbd,
    const float* __restrict__ Ww1, const float* __restrict__ bw1,
    const float* __restrict__ Ww2, const float* __restrict__ bw2,
    const float* __restrict__ Ww3, const float* __restrict__ bw3,
    const float* __restrict__ Ww4, const float* __restrict__ bw4,
    const float* __restrict__ Wp1, const float* __restrict__ bp1,
    const float* __restrict__ Wp2, const float* __restrict__ bp2,
    const float* __restrict__ Wp3, const float* __restrict__ bp3,
    const float* __restrict__ Wp4, const float* __restrict__ bp4,
    float* __restrict__ out, int N)
{
    __shared__ __align__(16) float S[off::TOTAL];
    const int tid = threadIdx.x;

    // zero everything (covers all pad lanes), then fill
    for (int k = tid; k < off::TOTAL; k += TPB) S[k] = 0.0f;
    __syncthreads();

    for (int t = tid; t < 60; t += TPB)  S[off::W1  + (t / 30) * 32 + (t % 30)] = Ww1[t];
    for (int t = tid; t < 30; t += TPB)  S[off::B1  + t] = bw1[t];
    for (int t = tid; t < 900; t += TPB) S[off::W2T + (t % 30) * 32 + (t / 30)] = Ww2[t];
    for (int t = tid; t < 30; t += TPB)  S[off::W2T + t * 32 + 30] = bw2[t];
    for (int t = tid; t < 900; t += TPB) S[off::W3T + (t % 30) * 32 + (t / 30)] = Ww3[t];
    for (int t = tid; t < 30; t += TPB)  S[off::W3T + t * 32 + 30] = bw3[t];
    for (int t = tid; t < 240; t += TPB) S[off::W4T + (t % 8) * 32 + (t / 8)]   = Ww4[t];
    for (int t = tid; t < 8;  t += TPB)  S[off::W4T + t * 32 + 30] = bw4[t];
    for (int t = tid; t < 30; t += TPB)  S[off::P1  + (t / 15) * 16 + (t % 15)] = Wp1[t];
    for (int t = tid; t < 15; t += TPB)  S[off::PB1 + t] = bp1[t];
    for (int t = tid; t < 225; t += TPB) S[off::P2T + (t % 15) * 16 + (t / 15)] = Wp2[t];
    for (int t = tid; t < 15; t += TPB)  S[off::P2T + t * 16 + 15] = bp2[t];
    for (int t = tid; t < 225; t += TPB) S[off::P3T + (t % 15) * 16 + (t / 15)] = Wp3[t];
    for (int t = tid; t < 15; t += TPB)  S[off::P3T + t * 16 + 15] = bp3[t];
    for (int t = tid; t < 60; t += TPB)  S[off::P4T + (t % 4) * 16 + (t / 4)]   = Wp4[t];
    for (int t = tid; t < 4;  t += TPB)  S[off::P4T + t * 16 + 15] = bp4[t];
    if (tid == 0) {
        S[off::IMV]     = imv[0];
        S[off::IMV + 1] = imv[1];
        S[off::LMB]     = lmbd[0];
    }
    __syncthreads();

    const int i = blockIdx.x * TPB + tid;
    if (i >= N) return;

    const float2 xv = reinterpret_cast<const float2*>(x)[i];
    const float x0 = xv.x, x1 = xv.y;

    // ---------- w MLP: 2 -> 30 -> 30 -> 30 -> 8, packed-k dot products ----------
    ull h2[16], g2[16];
    #pragma unroll
    for (int c = 0; c < 8; ++c) {
        float4 w0 = *reinterpret_cast<const float4*>(&S[off::W1 + 4 * c]);
        float4 w1 = *reinterpret_cast<const float4*>(&S[off::W1 + 32 + 4 * c]);
        float4 bb = *reinterpret_cast<const float4*>(&S[off::B1 + 4 * c]);
        float t0 = fast_tanhf(fmaf(x0, w0.x, fmaf(x1, w1.x, bb.x)));
        float t1 = fast_tanhf(fmaf(x0, w0.y, fmaf(x1, w1.y, bb.y)));
        float t2 = fast_tanhf(fmaf(x0, w0.z, fmaf(x1, w1.z, bb.z)));
        float t3 = fast_tanhf(fmaf(x0, w0.w, fmaf(x1, w1.w, bb.w)));
        h2[2 * c]     = pk2(t0, t1);
        h2[2 * c + 1] = pk2(t2, t3);
    }
    h2[15] = pk2(1.0f, 0.0f);            // bias lane / zero pad

    // layer 2: outputs in pairs (2m, 2m+1) for ILP; 16 FFMA2 per output
    #pragma unroll
    for (int m = 0; m < 15; ++m) {
        const ulonglong2* rA = reinterpret_cast<const ulonglong2*>(&S[off::W2T + (2 * m) * 32]);
        const ulonglong2* rB = reinterpret_cast<const ulonglong2*>(&S[off::W2T + (2 * m + 1) * 32]);
        ull a0 = 0, a1 = 0, b0 = 0, b1 = 0;
        #pragma unroll
        for (int c = 0; c < 8; ++c) {
            ulonglong2 wa = rA[c], wb = rB[c];
            a0 = ffma2(h2[2 * c],     wa.x, a0);
            a1 = ffma2(h2[2 * c + 1], wa.y, a1);
            b0 = ffma2(h2[2 * c],     wb.x, b0);
            b1 = ffma2(h2[2 * c + 1], wb.y, b1);
        }
        float alo, ahi, blo, bhi;
        upk2(fadd2(a0, a1), alo, ahi);
        upk2(fadd2(b0, b1), blo, bhi);
        g2[m] = pk2(fast_tanhf(alo + ahi), fast_tanhf(blo + bhi));
    }
    g2[15] = pk2(1.0f, 0.0f);

    // layer 3
    #pragma unroll
    for (int m = 0; m < 15; ++m) {
        const ulonglong2* rA = reinterpret_cast<const ulonglong2*>(&S[off::W3T + (2 * m) * 32]);
        const ulonglong2* rB = reinterpret_cast<const ulonglong2*>(&S[off::W3T + (2 * m + 1) * 32]);
        ull a0 = 0, a1 = 0, b0 = 0, b1 = 0;
        #pragma unroll
        for (int c = 0; c < 8; ++c) {
            ulonglong2 wa = rA[c], wb = rB[c];
            a0 = ffma2(g2[2 * c],     wa.x, a0);
            a1 = ffma2(g2[2 * c + 1], wa.y, a1);
            b0 = ffma2(g2[2 * c],     wb.x, b0);
            b1 = ffma2(g2[2 * c + 1], wb.y, b1);
        }
        float alo, ahi, blo, bhi;
        upk2(fadd2(a0, a1), alo, ahi);
        upk2(fadd2(b0, b1), blo, bhi);
        h2[m] = pk2(fast_tanhf(alo + ahi), fast_tanhf(blo + bhi));
    }
    h2[15] = pk2(1.0f, 0.0f);

    // layer 4: 8 outputs = 4 pairs
    float w[8];
    #pragma unroll
    for (int m = 0; m < 4; ++m) {
        const ulonglong2* rA = reinterpret_cast<const ulonglong2*>(&S[off::W4T + (2 * m) * 32]);
        const ulonglong2* rB = reinterpret_cast<const ulonglong2*>(&S[off::W4T + (2 * m + 1) * 32]);
        ull a0 = 0, a1 = 0, b0 = 0, b1 = 0;
        #pragma unroll
        for (int c = 0; c < 8; ++c) {
            ulonglong2 wa = rA[c], wb = rB[c];
            a0 = ffma2(h2[2 * c],     wa.x, a0);
            a1 = ffma2(h2[2 * c + 1], wa.y, a1);
            b0 = ffma2(h2[2 * c],     wb.x, b0);
            b1 = ffma2(h2[2 * c + 1], wb.y, b1);
        }
        float alo, ahi, blo, bhi;
        upk2(fadd2(a0, a1), alo, ahi);
        upk2(fadd2(b0, b1), blo, bhi);
        w[2 * m]     = alo + ahi;
        w[2 * m + 1] = blo + bhi;
    }

    // ---------- geometry ----------
    const float d0 = x0 - S[off::IMV], d1 = x1 - S[off::IMV + 1];
    const float r  = sqrtf(fmaf(d0, d0, d1 * d1));
    const float ir = __fdividef(1.0f, r);
    const float bx = d0 * ir, by = d1 * ir;

    const float t  = fminf(fmaxf(fmaf(2.5f, r, -1.25f), 0.0f), 1.0f);
    const float t3 = t * t * t;
    const float yita = fmaf(fmaf(fmaf(-6.0f, t, 15.0f), t, -10.0f), t3, 1.0f);

    // ---------- phi MLP: 2 -> 15 -> 15 -> 15 -> 4, packed-k ----------
    ull p2[8], q2[8];
    {
        float ps[16];
        #pragma unroll
        for (int c = 0; c < 4; ++c) {
            float4 w0 = *reinterpret_cast<const float4*>(&S[off::P1 + 4 * c]);
            float4 w1 = *reinterpret_cast<const float4*>(&S[off::P1 + 16 + 4 * c]);
            float4 bb = *reinterpret_cast<const float4*>(&S[off::PB1 + 4 * c]);
            ps[4 * c + 0] = fast_tanhf(fmaf(bx, w0.x, fmaf(by, w1.x, bb.x)));
            ps[4 * c + 1] = fast_tanhf(fmaf(bx, w0.y, fmaf(by, w1.y, bb.y)));
            ps[4 * c + 2] = fast_tanhf(fmaf(bx, w0.z, fmaf(by, w1.z, bb.z)));
            ps[4 * c + 3] = fast_tanhf(fmaf(bx, w0.w, fmaf(by, w1.w, bb.w)));
        }
        #pragma unroll
        for (int m = 0; m < 7; ++m) p2[m] = pk2(ps[2 * m], ps[2 * m + 1]);
        p2[7] = pk2(ps[14], 1.0f);       // last activation + bias lane
    }

    // phi layer 2: 7 pairs + 1 single; 8 FFMA2 per output
    #pragma unroll
    for (int m = 0; m < 7; ++m) {
        const ulonglong2* rA = reinterpret_cast<const ulonglong2*>(&S[off::P2T + (2 * m) * 16]);
        const ulonglong2* rB = reinterpret_cast<const ulonglong2*>(&S[off::P2T + (2 * m + 1) * 16]);
        ull a0 = 0, a1 = 0, b0 = 0, b1 = 0;
        #pragma unroll
        for (int c = 0; c < 4; ++c) {
            ulonglong2 wa = rA[c], wb = rB[c];
            a0 = ffma2(p2[2 * c],     wa.x, a0);
            a1 = ffma2(p2[2 * c + 1], wa.y, a1);
            b0 = ffma2(p2[2 * c],     wb.x, b0);
            b1 = ffma2(p2[2 * c + 1], wb.y, b1);
        }
        float alo, ahi, blo, bhi;
        upk2(fadd2(a0, a1), alo, ahi);
        upk2(fadd2(b0, b1), blo, bhi);
        q2[m] = pk2(fast_tanhf(alo + ahi), fast_tanhf(blo + bhi));
    }
    {
        const ulonglong2* rA = reinterpret_cast<const ulonglong2*>(&S[off::P2T + 14 * 16]);
        ull a0 = 0, a1 = 0;
        #pragma unroll
        for (int c = 0; c < 4; ++c) {
            ulonglong2 wa = rA[c];
            a0 = ffma2(p2[2 * c],     wa.x, a0);
            a1 = ffma2(p2[2 * c + 1], wa.y, a1);
        }
        float alo, ahi;
        upk2(fadd2(a0, a1), alo, ahi);
        q2[7] = pk2(fast_tanhf(alo + ahi), 1.0f);
    }

    // phi layer 3
    #pragma unroll
    for (int m = 0; m < 7; ++m) {
        const ulonglong2* rA = reinterpret_cast<const ulonglong2*>(&S[off::P3T + (2 * m) * 16]);
        const ulonglong2* rB = reinterpret_cast<const ulonglong2*>(&S[off::P3T + (2 * m + 1) * 16]);
        ull a0 = 0, a1 = 0, b0 = 0, b1 = 0;
        #pragma unroll
        for (int c = 0; c < 4; ++c) {
            ulonglong2 wa = rA[c], wb = rB[c];
            a0 = ffma2(q2[2 * c],     wa.x, a0);
            a1 = ffma2(q2[2 * c + 1], wa.y, a1);
            b0 = ffma2(q2[2 * c],     wb.x, b0);
            b1 = ffma2(q2[2 * c + 1], wb.y, b1);
        }
        float alo, ahi, blo, bhi;
        upk2(fadd2(a0, a1), alo, ahi);
        upk2(fadd2(b0, b1), blo, bhi);
        p2[m] = pk2(fast_tanhf(alo + ahi), fast_tanhf(blo + bhi));
    }
    {
        const ulonglong2* rA = reinterpret_cast<const ulonglong2*>(&S[off::P3T + 14 * 16]);
        ull a0 = 0, a1 = 0;
        #pragma unroll
        for (int c = 0; c < 4; ++c) {
            ulonglong2 wa = rA[c];
            a0 = ffma2(q2[2 * c],     wa.x, a0);
            a1 = ffma2(q2[2 * c + 1], wa.y, a1);
        }
        float alo, ahi;
        upk2(fadd2(a0, a1), alo, ahi);
        p2[7] = pk2(fast_tanhf(alo + ahi), 1.0f);
    }

    // phi layer 4: 4 outputs = 2 pairs
    float ph[4];
    #pragma unroll
    for (int m = 0; m < 2; ++m) {
        const ulonglong2* rA = reinterpret_cast<const ulonglong2*>(&S[off::P4T + (2 * m) * 16]);
        const ulonglong2* rB = reinterpret_cast<const ulonglong2*>(&S[off::P4T + (2 * m + 1) * 16]);
        ull a0 = 0, a1 = 0, b0 = 0, b1 = 0;
        #pragma unroll
        for (int c = 0; c < 4; ++c) {
            ulonglong2 wa = rA[c], wb = rB[c];
            a0 = ffma2(p2[2 * c],     wa.x, a0);
            a1 = ffma2(p2[2 * c + 1], wa.y, a1);
            b0 = ffma2(p2[2 * c],     wb.x, b0);
            b1 = ffma2(p2[2 * c + 1], wb.y, b1);
        }
        float alo, ahi, blo, bhi;
        upk2(fadd2(a0, a1), alo, ahi);
        upk2(fadd2(b0, b1), blo, bhi);
        ph[2 * m]     = alo + ahi;
        ph[2 * m + 1] = blo + bhi;
    }

    // ---------- vphi at x: r^k sin(k*theta), k = 0.5, 1.0, 1.5 ----------
    const float rr  = sqrtf(fmaf(x0, x0, x1 * x1));
    const float irr = __fdividef(1.0f, rr);
    const float cc  = x0 * irr, ss = x1 * irr;
    float sh, ch;
    half_angle(cc, ss, sh, ch);
    const float sqr = sqrtf(rr);
    const float vp0 = sqr * sh;
    const float vp1 = rr * ss;
    const float vp2 = (rr * sqr) * fmaf(ss, ch, cc * sh);

    // ---------- vphi_sig at x_ba ----------
    float shb, chb;
    half_angle(bx, by, shb, chb);
    const float vs2 = fmaf(by, chb, bx * shb);

    // ---------- combine ----------
    const float rp = w[0] + yita * w[4]
                   + fmaf(yita, w[5], w[1]) * vp0
                   + fmaf(yita, w[6], w[2]) * vp1
                   + fmaf(yita, w[7], w[3]) * vp2;
    const float sv = ph[0] + ph[1] * shb + ph[2] * by + ph[3] * vs2;

    const float lm = S[off::LMB];
    const float rl = (lm == 0.5f) ? sqrtf(r) : __powf(r, lm);

    out[i] = fmaf(sv * yita, rl, rp);
}

extern "C" void kernel_launch(void* const* d_in, const int* in_sizes, int n_in,
                              void* d_out, int out_size) {
    const float* x    = (const float*)d_in[0];
    const float* imv  = (const float*)d_in[1];
    const float* lmbd = (const float*)d_in[2];
    const float* Ww1  = (const float*)d_in[3];
    const float* bw1  = (const float*)d_in[4];
    const float* Ww2  = (const float*)d_in[5];
    const float* bw2  = (const float*)d_in[6];
    const float* Ww3  = (const float*)d_in[7];
    const float* bw3  = (const float*)d_in[8];
    const float* Ww4  = (const float*)d_in[9];
    const float* bw4  = (const float*)d_in[10];
    const float* Wp1  = (const float*)d_in[11];
    const float* bp1  = (const float*)d_in[12];
    const float* Wp2  = (const float*)d_in[13];
    const float* bp2  = (const float*)d_in[14];
    const float* Wp3  = (const float*)d_in[15];
    const float* bp3  = (const float*)d_in[16];
    const float* Wp4  = (const float*)d_in[17];
    const float* bp4  = (const float*)d_in[18];
    float* out = (float*)d_out;

    const int N = out_size;
    const int blocks = (N + TPB - 1) / TPB;
    mlp_interior_kernel<<<blocks, TPB>>>(
        x, imv, lmbd,
        Ww1, bw1, Ww2, bw2, Ww3, bw3, Ww4, bw4,
        Wp1, bp1, Wp2, bp2, Wp3, bp3, Wp4, bp4,
        out, N);
}